// round 1
// baseline (speedup 1.0000x reference)
#include <cuda_runtime.h>
#include <math.h>

#define OUTW 7
#define SPP 4
#define CCH 256
#define HH 128
#define WW 128
#define BB 4
#define NROI 2000
#define FIN (OUTW*OUTW*CCH)   /* 12544 */
#define FC 1024
#define NBIN (OUTW*OUTW)      /* 49 */

// ---------------- scratch (static device globals; no dynamic alloc) ----------
__device__ float g_dataT[(size_t)BB*HH*WW*CCH];      // [B,H,W,C]   64 MB
__device__ float g_xf[(size_t)NROI*FIN];             // pooled feats 100 MB
__device__ float g_h1m[(size_t)NROI*2048];           // [h1 | m1]
__device__ float g_h2[(size_t)NROI*FC];
__device__ float g_off[(size_t)NROI*2*NBIN];
__device__ float g_mask[(size_t)NROI*NBIN];
__device__ float g_wcat[(size_t)FIN*2048];           // [w1 | mw1]  103 MB
__device__ float g_bcat[2048];

// ---------------- transpose [B,C,H,W] -> [B,H,W,C] ---------------------------
__global__ void k_transpose(const float* __restrict__ data) {
    __shared__ float tile[32][33];
    int xt = blockIdx.x;           // x tile 0..3
    int by = blockIdx.y;           // b*128 + y, 0..511
    int ct = blockIdx.z;           // c tile 0..7
    int b = by >> 7, y = by & 127;
    int x0 = xt * 32, c0 = ct * 32;
    int tx = threadIdx.x, ty = threadIdx.y;  // 32 x 8
#pragma unroll
    for (int i = 0; i < 4; i++) {
        int c = c0 + ty + 8 * i;
        tile[ty + 8 * i][tx] =
            data[(((size_t)b * CCH + c) * HH + y) * WW + x0 + tx];
    }
    __syncthreads();
#pragma unroll
    for (int i = 0; i < 4; i++) {
        int x = x0 + ty + 8 * i;
        g_dataT[(((size_t)b * HH + y) * WW + x) * CCH + c0 + tx] =
            tile[tx][ty + 8 * i];
    }
}

// ---------------- concat w1|mw1 and b1|mb1 -----------------------------------
__global__ void k_wcat(const float* __restrict__ w1, const float* __restrict__ mw1,
                       const float* __restrict__ b1, const float* __restrict__ mb1) {
    size_t i = (size_t)blockIdx.x * blockDim.x + threadIdx.x;
    size_t total = (size_t)FIN * 1024;
    if (i < total) {
        size_t k = i / 1024, j = i % 1024;
        g_wcat[k * 2048 + j]        = w1[i];
        g_wcat[k * 2048 + 1024 + j] = mw1[i];
    }
    if (i < 1024) { g_bcat[i] = b1[i]; g_bcat[1024 + i] = mb1[i]; }
}

// ---------------- deform ROI pool (one 7x7 bin per block, thread = channel) --
__global__ void k_pool(const float* __restrict__ rois,
                       const float* __restrict__ offset,  // nullable
                       const float* __restrict__ mask,    // nullable
                       float* __restrict__ out) {
    int bidx = blockIdx.x;
    int n = bidx / NBIN;
    int bin = bidx % NBIN;
    int ph = bin / OUTW, pw = bin % OUTW;
    int tid = threadIdx.x;

    __shared__ int   sx0[16], sy0[16];
    __shared__ float sdx[16], sdy[16], sval[16];
    __shared__ int   sb;

    const float* r = rois + n * 5;
    if (tid < 16) {
        float sw = floorf(r[1] + 0.5f) * 0.0625f - 0.5f;
        float sh = floorf(r[2] + 0.5f) * 0.0625f - 0.5f;
        float ew = (floorf(r[3] + 0.5f) + 1.0f) * 0.0625f - 0.5f;
        float eh = (floorf(r[4] + 0.5f) + 1.0f) * 0.0625f - 0.5f;
        float rw = fmaxf(ew - sw, 0.1f);
        float rh = fmaxf(eh - sh, 0.1f);
        float bw = rw / 7.0f, bh = rh / 7.0f;
        float subw = bw / 4.0f, subh = bh / 4.0f;
        float ws0 = (float)pw * bw + sw;
        float hs0 = (float)ph * bh + sh;
        if (offset) {
            ws0 += offset[(size_t)n * 98 + bin] * 0.1f * rw;
            hs0 += offset[(size_t)n * 98 + 49 + bin] * 0.1f * rh;
        }
        int ix = tid & 3, iy = tid >> 2;
        float w = ws0 + (float)ix * subw;
        float h = hs0 + (float)iy * subh;
        bool valid = (w >= -0.5f) && (w <= (float)WW - 0.5f) &&
                     (h >= -0.5f) && (h <= (float)HH - 0.5f);
        float wc = fminf(fmaxf(w, 0.0f), (float)(WW - 1));
        float hc = fminf(fmaxf(h, 0.0f), (float)(HH - 1));
        int x0 = (int)floorf(wc);
        int y0 = (int)floorf(hc);
        sx0[tid] = x0; sy0[tid] = y0;
        sdx[tid] = wc - (float)x0;
        sdy[tid] = hc - (float)y0;
        sval[tid] = valid ? 1.0f : 0.0f;
        if (tid == 0) sb = (int)r[0];
    }
    __syncthreads();

    float cnt = 0.0f;
#pragma unroll
    for (int s = 0; s < 16; s++) cnt += sval[s];

    const float* base = g_dataT + (size_t)sb * (HH * WW * CCH);
    int c = tid;  // 256 threads = 256 channels
    float acc = 0.0f;
#pragma unroll
    for (int s = 0; s < 16; s++) {
        if (sval[s] > 0.0f) {
            int x0 = sx0[s], y0 = sy0[s];
            int x1 = min(x0 + 1, WW - 1), y1 = min(y0 + 1, HH - 1);
            float dx = sdx[s], dy = sdy[s];
            float v00 = base[((size_t)(y0 * WW + x0)) * CCH + c];
            float v01 = base[((size_t)(y0 * WW + x1)) * CCH + c];
            float v10 = base[((size_t)(y1 * WW + x0)) * CCH + c];
            float v11 = base[((size_t)(y1 * WW + x1)) * CCH + c];
            acc += (1.0f - dx) * (1.0f - dy) * v00 + dx * (1.0f - dy) * v01 +
                   (1.0f - dx) * dy * v10 + dx * dy * v11;
        }
    }
    float v = (cnt > 0.0f) ? acc / cnt : 0.0f;
    if (mask) v *= mask[(size_t)n * NBIN + bin];
    out[(size_t)n * FIN + (size_t)c * NBIN + bin] = v;
}

// ---------------- SGEMM: C = act(A @ B + bias) --------------------------------
// A: [M,K] row-major stride lda; B: [K,N] row-major stride ldb.
// act: 0 none, 1 relu, 2 sigmoid. K must be multiple of 8.
__global__ void k_sgemm(const float* __restrict__ A, int lda,
                        const float* __restrict__ B, int ldb,
                        const float* __restrict__ bias,
                        float* __restrict__ C, int ldc,
                        int M, int N, int K, int act) {
    const int BM = 128, BN = 128, BK = 8;
    __shared__ float As[BK][BM];
    __shared__ float Bs[BK][BN];
    int tid = threadIdx.x;                 // 256
    int bm = blockIdx.y * BM, bn = blockIdx.x * BN;
    int tx = tid % 16, ty = tid / 16;      // 16x16 threads, 8x8 micro tile

    float acc[8][8];
#pragma unroll
    for (int i = 0; i < 8; i++)
#pragma unroll
        for (int j = 0; j < 8; j++) acc[i][j] = 0.0f;

    int arow = tid >> 1;
    int acol = (tid & 1) * 4;
    int brow = tid >> 5;
    int bcol = (tid & 31) * 4;

    for (int k0 = 0; k0 < K; k0 += BK) {
        int m = bm + arow;
#pragma unroll
        for (int i = 0; i < 4; i++) {
            int kk = k0 + acol + i;
            As[acol + i][arow] = (m < M) ? A[(size_t)m * lda + kk] : 0.0f;
        }
        int kk = k0 + brow;
#pragma unroll
        for (int i = 0; i < 4; i++) {
            int nn = bn + bcol + i;
            Bs[brow][bcol + i] = (nn < N) ? B[(size_t)kk * ldb + nn] : 0.0f;
        }
        __syncthreads();
#pragma unroll
        for (int kki = 0; kki < BK; kki++) {
            float a[8], b[8];
            *(float4*)&a[0] = *(const float4*)&As[kki][ty * 8];
            *(float4*)&a[4] = *(const float4*)&As[kki][ty * 8 + 4];
            *(float4*)&b[0] = *(const float4*)&Bs[kki][tx * 8];
            *(float4*)&b[4] = *(const float4*)&Bs[kki][tx * 8 + 4];
#pragma unroll
            for (int i = 0; i < 8; i++)
#pragma unroll
                for (int j = 0; j < 8; j++) acc[i][j] += a[i] * b[j];
        }
        __syncthreads();
    }

#pragma unroll
    for (int i = 0; i < 8; i++) {
        int m = bm + ty * 8 + i;
        if (m >= M) continue;
#pragma unroll
        for (int j = 0; j < 8; j++) {
            int nn = bn + tx * 8 + j;
            if (nn < N) {
                float v = acc[i][j] + bias[nn];
                if (act == 1) v = fmaxf(v, 0.0f);
                else if (act == 2) v = 1.0f / (1.0f + expf(-v));
                C[(size_t)m * ldc + nn] = v;
            }
        }
    }
}

// ---------------- launch ------------------------------------------------------
extern "C" void kernel_launch(void* const* d_in, const int* in_sizes, int n_in,
                              void* d_out, int out_size) {
    const float* data = (const float*)d_in[0];
    const float* rois = (const float*)d_in[1];
    const float* w1   = (const float*)d_in[2];
    const float* b1   = (const float*)d_in[3];
    const float* w2   = (const float*)d_in[4];
    const float* b2   = (const float*)d_in[5];
    const float* w3   = (const float*)d_in[6];
    const float* b3   = (const float*)d_in[7];
    const float* mw1  = (const float*)d_in[8];
    const float* mb1  = (const float*)d_in[9];
    const float* mw2  = (const float*)d_in[10];
    const float* mb2  = (const float*)d_in[11];
    float* out = (float*)d_out;

    float *xf, *h1m, *h2, *off, *maskb, *wcat, *bcat;
    cudaGetSymbolAddress((void**)&xf,    g_xf);
    cudaGetSymbolAddress((void**)&h1m,   g_h1m);
    cudaGetSymbolAddress((void**)&h2,    g_h2);
    cudaGetSymbolAddress((void**)&off,   g_off);
    cudaGetSymbolAddress((void**)&maskb, g_mask);
    cudaGetSymbolAddress((void**)&wcat,  g_wcat);
    cudaGetSymbolAddress((void**)&bcat,  g_bcat);

    // 1. layout transform + weight concat
    k_transpose<<<dim3(4, 512, 8), dim3(32, 8)>>>(data);
    {
        size_t total = (size_t)FIN * 1024;
        int blocks = (int)((total + 255) / 256);
        k_wcat<<<blocks, 256>>>(w1, mw1, b1, mb1);
    }

    // 2. pool pass 1 (no offset, no mask) -> xf  [N, c*49+bin]
    k_pool<<<NROI * NBIN, 256>>>(rois, nullptr, nullptr, xf);

    // 3. G1: [2000,12544] @ [12544,2048] -> h1m (relu)
    k_sgemm<<<dim3(2048 / 128, (NROI + 127) / 128), 256>>>(
        xf, FIN, wcat, 2048, bcat, h1m, 2048, NROI, 2048, FIN, 1);

    // 4. G2: h1 @ w2 -> h2 (relu)
    k_sgemm<<<dim3(1024 / 128, (NROI + 127) / 128), 256>>>(
        h1m, 2048, w2, 1024, b2, h2, 1024, NROI, 1024, 1024, 1);

    // 5. G3: h2 @ w3 -> offsets [2000,98] (linear)
    k_sgemm<<<dim3(1, (NROI + 127) / 128), 256>>>(
        h2, 1024, w3, 98, b3, off, 98, NROI, 98, 1024, 0);

    // 6. G4: m1 @ mw2 -> mask [2000,49] (sigmoid)
    k_sgemm<<<dim3(1, (NROI + 127) / 128), 256>>>(
        h1m + 1024, 2048, mw2, 49, mb2, maskb, 49, NROI, 49, 1024, 2);

    // 7. pool pass 2 (offset + mask) -> d_out [N,C,7,7]
    k_pool<<<NROI * NBIN, 256>>>(rois, off, maskb, out);
}

// round 2
// speedup vs baseline: 2.0879x; 2.0879x over previous
#include <cuda_runtime.h>
#include <math.h>
#include <stdint.h>

#define OUTW 7
#define SPP 4
#define CCH 256
#define HH 128
#define WW 128
#define BB 4
#define NROI 2000
#define FIN (OUTW*OUTW*CCH)   /* 12544 */
#define FC 1024
#define NBIN (OUTW*OUTW)      /* 49 */

// ---------------- scratch (static device globals; no dynamic alloc) ----------
__device__ float g_dataT[(size_t)BB*HH*WW*CCH];      // [B,H,W,C]   64 MB
__device__ float g_xf[(size_t)NROI*FIN];             // pooled feats 100 MB
__device__ float g_h1[(size_t)NROI*FC];
__device__ float g_m1[(size_t)NROI*FC];
__device__ float g_h2[(size_t)NROI*FC];
__device__ float g_off[(size_t)NROI*2*NBIN];
__device__ float g_mask[(size_t)NROI*NBIN];

// ---------------- transpose [B,C,H,W] -> [B,H,W,C] ---------------------------
__global__ void k_transpose(const float* __restrict__ data) {
    __shared__ float tile[32][33];
    int xt = blockIdx.x;           // x tile 0..3
    int by = blockIdx.y;           // b*128 + y, 0..511
    int ct = blockIdx.z;           // c tile 0..7
    int b = by >> 7, y = by & 127;
    int x0 = xt * 32, c0 = ct * 32;
    int tx = threadIdx.x, ty = threadIdx.y;  // 32 x 8
#pragma unroll
    for (int i = 0; i < 4; i++) {
        int c = c0 + ty + 8 * i;
        tile[ty + 8 * i][tx] =
            data[(((size_t)b * CCH + c) * HH + y) * WW + x0 + tx];
    }
    __syncthreads();
#pragma unroll
    for (int i = 0; i < 4; i++) {
        int x = x0 + ty + 8 * i;
        g_dataT[(((size_t)b * HH + y) * WW + x) * CCH + c0 + tx] =
            tile[tx][ty + 8 * i];
    }
}

// ---------------- deform ROI pool (one 7x7 bin per block, thread = channel) --
__global__ void k_pool(const float* __restrict__ rois,
                       const float* __restrict__ offset,  // nullable
                       const float* __restrict__ mask,    // nullable
                       float* __restrict__ out) {
    int bidx = blockIdx.x;
    int n = bidx / NBIN;
    int bin = bidx % NBIN;
    int ph = bin / OUTW, pw = bin % OUTW;
    int tid = threadIdx.x;

    __shared__ int   sx0[16], sy0[16];
    __shared__ float sdx[16], sdy[16], sval[16];
    __shared__ int   sb;

    const float* r = rois + n * 5;
    if (tid < 16) {
        float sw = floorf(r[1] + 0.5f) * 0.0625f - 0.5f;
        float sh = floorf(r[2] + 0.5f) * 0.0625f - 0.5f;
        float ew = (floorf(r[3] + 0.5f) + 1.0f) * 0.0625f - 0.5f;
        float eh = (floorf(r[4] + 0.5f) + 1.0f) * 0.0625f - 0.5f;
        float rw = fmaxf(ew - sw, 0.1f);
        float rh = fmaxf(eh - sh, 0.1f);
        float bw = rw / 7.0f, bh = rh / 7.0f;
        float subw = bw / 4.0f, subh = bh / 4.0f;
        float ws0 = (float)pw * bw + sw;
        float hs0 = (float)ph * bh + sh;
        if (offset) {
            ws0 += offset[(size_t)n * 98 + bin] * 0.1f * rw;
            hs0 += offset[(size_t)n * 98 + 49 + bin] * 0.1f * rh;
        }
        int ix = tid & 3, iy = tid >> 2;
        float w = ws0 + (float)ix * subw;
        float h = hs0 + (float)iy * subh;
        bool valid = (w >= -0.5f) && (w <= (float)WW - 0.5f) &&
                     (h >= -0.5f) && (h <= (float)HH - 0.5f);
        float wc = fminf(fmaxf(w, 0.0f), (float)(WW - 1));
        float hc = fminf(fmaxf(h, 0.0f), (float)(HH - 1));
        int x0 = (int)floorf(wc);
        int y0 = (int)floorf(hc);
        sx0[tid] = x0; sy0[tid] = y0;
        sdx[tid] = wc - (float)x0;
        sdy[tid] = hc - (float)y0;
        sval[tid] = valid ? 1.0f : 0.0f;
        if (tid == 0) sb = (int)r[0];
    }
    __syncthreads();

    float cnt = 0.0f;
#pragma unroll
    for (int s = 0; s < 16; s++) cnt += sval[s];

    const float* base = g_dataT + (size_t)sb * (HH * WW * CCH);
    int c = tid;  // 256 threads = 256 channels
    float acc = 0.0f;
#pragma unroll
    for (int s = 0; s < 16; s++) {
        if (sval[s] > 0.0f) {
            int x0 = sx0[s], y0 = sy0[s];
            int x1 = min(x0 + 1, WW - 1), y1 = min(y0 + 1, HH - 1);
            float dx = sdx[s], dy = sdy[s];
            float v00 = base[((size_t)(y0 * WW + x0)) * CCH + c];
            float v01 = base[((size_t)(y0 * WW + x1)) * CCH + c];
            float v10 = base[((size_t)(y1 * WW + x0)) * CCH + c];
            float v11 = base[((size_t)(y1 * WW + x1)) * CCH + c];
            acc += (1.0f - dx) * (1.0f - dy) * v00 + dx * (1.0f - dy) * v01 +
                   (1.0f - dx) * dy * v10 + dx * dy * v11;
        }
    }
    float v = (cnt > 0.0f) ? acc / cnt : 0.0f;
    if (mask) v *= mask[(size_t)n * NBIN + bin];
    out[(size_t)n * FIN + (size_t)c * NBIN + bin] = v;
}

// ---------------- tf32 helpers ------------------------------------------------
__device__ __forceinline__ uint32_t f2tf32(float x) {
    uint32_t u;
    asm("cvt.rna.tf32.f32 %0, %1;" : "=r"(u) : "f"(x));
    return u;
}

__device__ __forceinline__ void mma_tf32(float* c, const uint32_t* a, const uint32_t* b) {
    asm volatile(
        "mma.sync.aligned.m16n8k8.row.col.f32.tf32.tf32.f32 "
        "{%0,%1,%2,%3}, {%4,%5,%6,%7}, {%8,%9}, {%0,%1,%2,%3};"
        : "+f"(c[0]), "+f"(c[1]), "+f"(c[2]), "+f"(c[3])
        : "r"(a[0]), "r"(a[1]), "r"(a[2]), "r"(a[3]), "r"(b[0]), "r"(b[1]));
}

// ---------------- tf32 tensor-core GEMM: C = act(A @ B + bias) ----------------
// A: [M,K] row-major (lda), B: [K,N] row-major (ldb). Requires K%16==0, N%128==0.
// If gridDim.z==2 and blockIdx.z==1, uses B2/bias2/C2 (fused second head).
// act: 0 none, 1 relu, 2 sigmoid.
#define LDA_S 20
#define LDB_S 136
__global__ void __launch_bounds__(256) k_gemm_tf32(
    const float* __restrict__ A, int lda,
    const float* __restrict__ B, int ldb,
    const float* __restrict__ bias,
    float* __restrict__ C, int ldc,
    const float* __restrict__ B2,
    const float* __restrict__ bias2,
    float* __restrict__ C2,
    int M, int N, int K, int act) {
    if (blockIdx.z == 1) { B = B2; bias = bias2; C = C2; }

    __shared__ uint32_t As[2][128 * LDA_S];
    __shared__ uint32_t Bs[2][16 * LDB_S];

    int tid = threadIdx.x;
    int warp = tid >> 5, lane = tid & 31;
    int g = lane >> 2, t = lane & 3;
    int wm = warp >> 2;       // 0..1  (64-row warp tile)
    int wn = warp & 3;        // 0..3  (32-col warp tile)
    int bm = blockIdx.y * 128, bn = blockIdx.x * 128;

    // global load mapping
    int arow = tid >> 2;              // 0..63
    int akc  = (tid & 3) * 4;         // 0,4,8,12
    int bkr  = tid >> 5;              // 0..7
    int bn4  = (lane) * 4;            // 0..124

    float acc[4][4][4];
#pragma unroll
    for (int i = 0; i < 4; i++)
#pragma unroll
        for (int j = 0; j < 4; j++)
#pragma unroll
            for (int q = 0; q < 4; q++) acc[i][j][q] = 0.0f;

    float4 a4[2], b4[2];
    const float4 z4 = make_float4(0.f, 0.f, 0.f, 0.f);

    // prologue: load tile 0
    {
#pragma unroll
        for (int r = 0; r < 2; r++) {
            int m = bm + arow + r * 64;
            a4[r] = (m < M) ? *(const float4*)&A[(size_t)m * lda + akc] : z4;
        }
#pragma unroll
        for (int r = 0; r < 2; r++) {
            int k = bkr + r * 8;
            b4[r] = *(const float4*)&B[(size_t)k * ldb + bn + bn4];
        }
#pragma unroll
        for (int r = 0; r < 2; r++) {
            const float* f = (const float*)&a4[r];
            uint4 u = make_uint4(f2tf32(f[0]), f2tf32(f[1]), f2tf32(f[2]), f2tf32(f[3]));
            *(uint4*)&As[0][(arow + r * 64) * LDA_S + akc] = u;
        }
#pragma unroll
        for (int r = 0; r < 2; r++) {
            const float* f = (const float*)&b4[r];
            uint4 u = make_uint4(f2tf32(f[0]), f2tf32(f[1]), f2tf32(f[2]), f2tf32(f[3]));
            *(uint4*)&Bs[0][(bkr + r * 8) * LDB_S + bn4] = u;
        }
    }
    __syncthreads();

    int ntiles = K / 16;
    for (int kt = 0; kt < ntiles; kt++) {
        int cur = kt & 1, nxt = cur ^ 1;
        bool has = (kt + 1) < ntiles;
        if (has) {
            int k0 = (kt + 1) * 16;
#pragma unroll
            for (int r = 0; r < 2; r++) {
                int m = bm + arow + r * 64;
                a4[r] = (m < M) ? *(const float4*)&A[(size_t)m * lda + k0 + akc] : z4;
            }
#pragma unroll
            for (int r = 0; r < 2; r++) {
                int k = k0 + bkr + r * 8;
                b4[r] = *(const float4*)&B[(size_t)k * ldb + bn + bn4];
            }
        }

        // compute on cur
#pragma unroll
        for (int ko = 0; ko < 2; ko++) {
            int kb = ko * 8;
            uint32_t af[4][4], bf[4][2];
#pragma unroll
            for (int i = 0; i < 4; i++) {
                int m0 = wm * 64 + i * 16;
                af[i][0] = As[cur][(m0 + g) * LDA_S + kb + t];
                af[i][1] = As[cur][(m0 + g + 8) * LDA_S + kb + t];
                af[i][2] = As[cur][(m0 + g) * LDA_S + kb + t + 4];
                af[i][3] = As[cur][(m0 + g + 8) * LDA_S + kb + t + 4];
            }
#pragma unroll
            for (int j = 0; j < 4; j++) {
                int n0 = wn * 32 + j * 8;
                bf[j][0] = Bs[cur][(kb + t) * LDB_S + n0 + g];
                bf[j][1] = Bs[cur][(kb + t + 4) * LDB_S + n0 + g];
            }
#pragma unroll
            for (int i = 0; i < 4; i++)
#pragma unroll
                for (int j = 0; j < 4; j++)
                    mma_tf32(acc[i][j], af[i], bf[j]);
        }

        if (has) {
#pragma unroll
            for (int r = 0; r < 2; r++) {
                const float* f = (const float*)&a4[r];
                uint4 u = make_uint4(f2tf32(f[0]), f2tf32(f[1]), f2tf32(f[2]), f2tf32(f[3]));
                *(uint4*)&As[nxt][(arow + r * 64) * LDA_S + akc] = u;
            }
#pragma unroll
            for (int r = 0; r < 2; r++) {
                const float* f = (const float*)&b4[r];
                uint4 u = make_uint4(f2tf32(f[0]), f2tf32(f[1]), f2tf32(f[2]), f2tf32(f[3]));
                *(uint4*)&Bs[nxt][(bkr + r * 8) * LDB_S + bn4] = u;
            }
        }
        __syncthreads();
    }

    // epilogue
#pragma unroll
    for (int i = 0; i < 4; i++) {
        int r0 = bm + wm * 64 + i * 16 + g;
        int r1 = r0 + 8;
#pragma unroll
        for (int j = 0; j < 4; j++) {
            int c0 = bn + wn * 32 + j * 8 + 2 * t;
            float bv0 = bias[c0], bv1 = bias[c0 + 1];
            float v;
            if (r0 < M) {
                v = acc[i][j][0] + bv0;
                if (act == 1) v = fmaxf(v, 0.0f);
                else if (act == 2) v = 1.0f / (1.0f + expf(-v));
                C[(size_t)r0 * ldc + c0] = v;
                v = acc[i][j][1] + bv1;
                if (act == 1) v = fmaxf(v, 0.0f);
                else if (act == 2) v = 1.0f / (1.0f + expf(-v));
                C[(size_t)r0 * ldc + c0 + 1] = v;
            }
            if (r1 < M) {
                v = acc[i][j][2] + bv0;
                if (act == 1) v = fmaxf(v, 0.0f);
                else if (act == 2) v = 1.0f / (1.0f + expf(-v));
                C[(size_t)r1 * ldc + c0] = v;
                v = acc[i][j][3] + bv1;
                if (act == 1) v = fmaxf(v, 0.0f);
                else if (act == 2) v = 1.0f / (1.0f + expf(-v));
                C[(size_t)r1 * ldc + c0 + 1] = v;
            }
        }
    }
}

// ---------------- fallback scalar SGEMM (small-N heads) -----------------------
__global__ void k_sgemm(const float* __restrict__ A, int lda,
                        const float* __restrict__ B, int ldb,
                        const float* __restrict__ bias,
                        float* __restrict__ C, int ldc,
                        int M, int N, int K, int act) {
    const int BM = 128, BN = 128, BK = 8;
    __shared__ float As[BK][BM];
    __shared__ float Bs[BK][BN];
    int tid = threadIdx.x;
    int bm = blockIdx.y * BM, bn = blockIdx.x * BN;
    int tx = tid % 16, ty = tid / 16;

    float acc[8][8];
#pragma unroll
    for (int i = 0; i < 8; i++)
#pragma unroll
        for (int j = 0; j < 8; j++) acc[i][j] = 0.0f;

    int arow = tid >> 1;
    int acol = (tid & 1) * 4;
    int brow = tid >> 5;
    int bcol = (tid & 31) * 4;

    for (int k0 = 0; k0 < K; k0 += BK) {
        int m = bm + arow;
#pragma unroll
        for (int i = 0; i < 4; i++) {
            int kk = k0 + acol + i;
            As[acol + i][arow] = (m < M) ? A[(size_t)m * lda + kk] : 0.0f;
        }
        int kk = k0 + brow;
#pragma unroll
        for (int i = 0; i < 4; i++) {
            int nn = bn + bcol + i;
            Bs[brow][bcol + i] = (nn < N) ? B[(size_t)kk * ldb + nn] : 0.0f;
        }
        __syncthreads();
#pragma unroll
        for (int kki = 0; kki < BK; kki++) {
            float a[8], b[8];
            *(float4*)&a[0] = *(const float4*)&As[kki][ty * 8];
            *(float4*)&a[4] = *(const float4*)&As[kki][ty * 8 + 4];
            *(float4*)&b[0] = *(const float4*)&Bs[kki][tx * 8];
            *(float4*)&b[4] = *(const float4*)&Bs[kki][tx * 8 + 4];
#pragma unroll
            for (int i = 0; i < 8; i++)
#pragma unroll
                for (int j = 0; j < 8; j++) acc[i][j] += a[i] * b[j];
        }
        __syncthreads();
    }

#pragma unroll
    for (int i = 0; i < 8; i++) {
        int m = bm + ty * 8 + i;
        if (m >= M) continue;
#pragma unroll
        for (int j = 0; j < 8; j++) {
            int nn = bn + tx * 8 + j;
            if (nn < N) {
                float v = acc[i][j] + bias[nn];
                if (act == 1) v = fmaxf(v, 0.0f);
                else if (act == 2) v = 1.0f / (1.0f + expf(-v));
                C[(size_t)m * ldc + nn] = v;
            }
        }
    }
}

// ---------------- launch ------------------------------------------------------
extern "C" void kernel_launch(void* const* d_in, const int* in_sizes, int n_in,
                              void* d_out, int out_size) {
    const float* data = (const float*)d_in[0];
    const float* rois = (const float*)d_in[1];
    const float* w1   = (const float*)d_in[2];
    const float* b1   = (const float*)d_in[3];
    const float* w2   = (const float*)d_in[4];
    const float* b2   = (const float*)d_in[5];
    const float* w3   = (const float*)d_in[6];
    const float* b3   = (const float*)d_in[7];
    const float* mw1  = (const float*)d_in[8];
    const float* mb1  = (const float*)d_in[9];
    const float* mw2  = (const float*)d_in[10];
    const float* mb2  = (const float*)d_in[11];
    float* out = (float*)d_out;

    float *xf, *h1, *m1, *h2, *off, *maskb;
    cudaGetSymbolAddress((void**)&xf,    g_xf);
    cudaGetSymbolAddress((void**)&h1,    g_h1);
    cudaGetSymbolAddress((void**)&m1,    g_m1);
    cudaGetSymbolAddress((void**)&h2,    g_h2);
    cudaGetSymbolAddress((void**)&off,   g_off);
    cudaGetSymbolAddress((void**)&maskb, g_mask);

    // 1. layout transform
    k_transpose<<<dim3(4, 512, 8), dim3(32, 8)>>>(data);

    // 2. pool pass 1 (no offset, no mask) -> xf  [N, c*49+bin]
    k_pool<<<NROI * NBIN, 256>>>(rois, nullptr, nullptr, xf);

    // 3. G1 fused: xf @ w1 -> h1 (relu)  |  xf @ mw1 -> m1 (relu)   [tf32 TC]
    k_gemm_tf32<<<dim3(FC / 128, (NROI + 127) / 128, 2), 256>>>(
        xf, FIN, w1, FC, b1, h1, FC, mw1, mb1, m1,
        NROI, FC, FIN, 1);

    // 4. G2: h1 @ w2 -> h2 (relu)   [tf32 TC]
    k_gemm_tf32<<<dim3(FC / 128, (NROI + 127) / 128, 1), 256>>>(
        h1, FC, w2, FC, b2, h2, FC, nullptr, nullptr, nullptr,
        NROI, FC, FC, 1);

    // 5. G3: h2 @ w3 -> offsets [2000,98] (linear)
    k_sgemm<<<dim3(1, (NROI + 127) / 128), 256>>>(
        h2, FC, w3, 98, b3, off, 98, NROI, 98, FC, 0);

    // 6. G4: m1 @ mw2 -> mask [2000,49] (sigmoid)
    k_sgemm<<<dim3(1, (NROI + 127) / 128), 256>>>(
        m1, FC, mw2, 49, mb2, maskb, 49, NROI, 49, FC, 2);

    // 7. pool pass 2 (offset + mask) -> d_out [N,C,7,7]
    k_pool<<<NROI * NBIN, 256>>>(rois, off, maskb, out);
}